// round 9
// baseline (speedup 1.0000x reference)
#include <cuda_runtime.h>
#include <math.h>

#define N_NODES 20000
#define N_EDGES 400000
#define KDIM 4160
typedef unsigned long long ull;

// ---------------- device globals --------------------------------------------
__device__ float g_S[(size_t)N_NODES * KDIM];
__device__ float g_hid[(size_t)N_EDGES * 128];   // relu(ea@W1+b1), layer-shared
__device__ float g_B[2][KDIM * 16];
__device__ float g_h0[N_NODES * 16];
__device__ float g_h1[N_NODES * 16];
__device__ int   g_deg[N_NODES];
__device__ int   g_cursor[N_NODES];
__device__ int   g_off[N_NODES + 1];
__device__ int2  g_es[N_EDGES];                  // (edge id, src) sorted by dst

__device__ __forceinline__ float* pick_buf(int s, float* ext) {
    if (s == 0) return g_h0;
    if (s == 1) return g_h1;
    return ext;
}

// ---------------- f32x2 helpers ----------------------------------------------
__device__ __forceinline__ ull pack2(float a, float b) {
    ull r; asm("mov.b64 %0, {%1, %2};" : "=l"(r) : "f"(a), "f"(b)); return r;
}
__device__ __forceinline__ void unpack2(ull v, float& a, float& b) {
    asm("mov.b64 {%0, %1}, %2;" : "=f"(a), "=f"(b) : "l"(v));
}
__device__ __forceinline__ ull fma2(ull a, ull b, ull c) {
    ull d; asm("fma.rn.f32x2 %0, %1, %2, %3;" : "=l"(d) : "l"(a), "l"(b), "l"(c));
    return d;
}
__device__ __forceinline__ ull add2(ull a, ull b) {
    ull d; asm("add.rn.f32x2 %0, %1, %2;" : "=l"(d) : "l"(a), "l"(b)); return d;
}

// ---------------- launch 0: degree count + node embedding --------------------
#define COUNT_BLOCKS 1563
__global__ void k_count_embed(const int* __restrict__ ei,
                              const float* __restrict__ x,
                              const float* __restrict__ Wn,
                              const float* __restrict__ bn) {
    int b = blockIdx.x;
    if (b < COUNT_BLOCKS) {
        int e = b * 256 + threadIdx.x;
        if (e < N_EDGES) atomicAdd(&g_deg[ei[N_EDGES + e]], 1);
    } else {
        __shared__ float sW[256];
        __shared__ float sb[16];
        int tid = threadIdx.x;
        sW[tid] = Wn[tid];
        if (tid < 16) sb[tid] = bn[tid];
        __syncthreads();
        int n = (b - COUNT_BLOCKS) * 256 + tid;
        if (n >= N_NODES) return;
        float xi[16];
        const float4* xp = (const float4*)(x + (size_t)n * 16);
#pragma unroll
        for (int q = 0; q < 4; q++) {
            float4 v = xp[q];
            xi[4*q] = v.x; xi[4*q+1] = v.y; xi[4*q+2] = v.z; xi[4*q+3] = v.w;
        }
        float o[16];
#pragma unroll
        for (int d = 0; d < 16; d++) {
            float acc = sb[d];
#pragma unroll
            for (int k = 0; k < 16; k++) acc = fmaf(xi[k], sW[k*16+d], acc);
            o[d] = fmaxf(acc, 0.f);
        }
        float4* op = (float4*)(g_h0 + (size_t)n * 16);
#pragma unroll
        for (int q = 0; q < 4; q++)
            op[q] = make_float4(o[4*q], o[4*q+1], o[4*q+2], o[4*q+3]);
    }
}

// ---------------- launch 1: prefix scan --------------------------------------
__global__ void __launch_bounds__(1024) k_scan() {
    __shared__ int sm[1024];
    int t = threadIdx.x;
    int base = t * 20;
    int vals[20];
    int local = 0;
#pragma unroll
    for (int i = 0; i < 20; i++) {
        int idx = base + i;
        vals[i] = (idx < N_NODES) ? g_deg[idx] : 0;
        local += vals[i];
    }
    sm[t] = local;
    __syncthreads();
    for (int off = 1; off < 1024; off <<= 1) {
        int v = (t >= off) ? sm[t - off] : 0;
        __syncthreads();
        sm[t] += v;
        __syncthreads();
    }
    int run = sm[t] - local;
#pragma unroll
    for (int i = 0; i < 20; i++) {
        int idx = base + i;
        if (idx < N_NODES) { g_off[idx] = run; run += vals[i]; g_cursor[idx] = 0; }
    }
    if (t == 0) g_off[N_NODES] = N_EDGES;
}

// ---------------- launch 2: fused fill + hid + init --------------------------
#define HID_BLOCKS 6250          // 64 edges per block
#define NB_ELEM (2 * KDIM * 16)
#define INIT_ELEMS (NB_ELEM + 2 * N_NODES * 16)
#define INIT_BLOCKS ((INIT_ELEMS + 255) / 256)

__global__ void __launch_bounds__(256) k_prep(
    const int* __restrict__ ei, const float* __restrict__ ea,
    const float* __restrict__ W1, const float* __restrict__ b1,
    const float* __restrict__ W2, const float* __restrict__ b2,
    const float* __restrict__ root1, const float* __restrict__ root2,
    const float* __restrict__ bias1, const float* __restrict__ bias2,
    int sout2, float* ext) {
    int b = blockIdx.x;
    int tid = threadIdx.x;
    if (b < COUNT_BLOCKS) {
        // fill dst-sorted edge list (+ re-zero deg)
        int e = b * 256 + tid;
        if (e < N_EDGES) {
            int d = ei[N_EDGES + e];
            int pos = g_off[d] + atomicAdd(&g_cursor[d], 1);
            g_es[pos] = make_int2(e, ei[e]);
        }
        if (e < N_NODES) g_deg[e] = 0;
    } else if (b < COUNT_BLOCKS + HID_BLOCKS) {
        // hid = relu(ea @ W1 + b1), 64 edges per block
        __shared__ float sEA[64 * 17];
        __shared__ float sW1[16 * 128];
        __shared__ float sB1[128];
        int e0 = (b - COUNT_BLOCKS) * 64;
        for (int idx = tid; idx < 64 * 16; idx += 256) {
            int e = idx >> 4, k = idx & 15;
            sEA[e*17 + k] = ea[(size_t)(e0 + e)*16 + k];
        }
        for (int idx = tid; idx < 2048; idx += 256) sW1[idx] = W1[idx];
        if (tid < 128) sB1[tid] = b1[tid];
        __syncthreads();
        int el = tid >> 2;      // edge in block
        int p  = tid & 3;       // output quarter
        float a[16];
#pragma unroll
        for (int k = 0; k < 16; k++) a[k] = sEA[el*17 + k];
        float* outp = g_hid + (size_t)(e0 + el) * 128 + p * 32;
#pragma unroll
        for (int uu = 0; uu < 32; uu += 4) {
            int ub = p*32 + uu;
            float c0 = sB1[ub+0], c1 = sB1[ub+1], c2 = sB1[ub+2], c3 = sB1[ub+3];
#pragma unroll
            for (int k = 0; k < 16; k++) {
                float av = a[k];
                const float* wr = &sW1[k*128 + ub];
                c0 = fmaf(av, wr[0], c0);
                c1 = fmaf(av, wr[1], c1);
                c2 = fmaf(av, wr[2], c2);
                c3 = fmaf(av, wr[3], c3);
            }
            *(float4*)(outp + uu) = make_float4(fmaxf(c0, 0.f), fmaxf(c1, 0.f),
                                                fmaxf(c2, 0.f), fmaxf(c3, 0.f));
        }
    } else {
        // build B (both layers) + seed outputs with bias
        int idx = (b - COUNT_BLOCKS - HID_BLOCKS) * 256 + tid;
        if (idx < NB_ELEM) {
            int layer = idx / (KDIM * 16);
            int m = idx % (KDIM * 16);
            int kj = m >> 4, d = m & 15;
            const float* root = layer ? root2 : root1;
            float v = 0.f;
            if (kj < 2048) {                       // T rows
                int k = kj >> 4, j = kj & 15;
                v = W2[(size_t)k * 512 + (16 + j) * 16 + d];
            } else if (kj < 4096) {                // Hsum*h rows
                int mm = kj - 2048;
                int k = mm >> 4, r = mm & 15;
                v = W2[(size_t)k * 512 + r * 16 + d];
            } else if (kj < 4112) {
                v = b2[(kj - 4096) * 16 + d];
            } else if (kj < 4128) {
                v = b2[256 + (kj - 4112) * 16 + d];
            } else if (kj < 4144) {
                v = root[(kj - 4128) * 16 + d];
            }
            g_B[layer][kj * 16 + d] = v;
        } else if (idx < NB_ELEM + N_NODES * 16) {
            int m = idx - NB_ELEM;
            g_h1[m] = bias1[m & 15];
        } else if (idx < INIT_ELEMS) {
            int m = idx - NB_ELEM - N_NODES * 16;
            float* h2 = pick_buf(sout2, ext);
            h2[m] = bias2[m & 15];
        }
    }
}

// ---------------- edge pass: 1 warp per node, hid precomputed ----------------
__global__ void __launch_bounds__(256, 2) k_edge_pass(int sin) {
    const float* hin = (sin == 0) ? g_h0 : g_h1;
    int tid = threadIdx.x, wid = tid >> 5, l = tid & 31;
    int n = blockIdx.x * 8 + wid;

    int start = g_off[n], end = g_off[n + 1];

    ull T[4][8];
#pragma unroll
    for (int kk = 0; kk < 4; kk++)
#pragma unroll
        for (int q = 0; q < 8; q++) T[kk][q] = 0ull;
    ull Hs[8];
#pragma unroll
    for (int q = 0; q < 8; q++) Hs[q] = 0ull;
    float hs0 = 0.f, hs1 = 0.f, hs2 = 0.f, hs3 = 0.f;  // Hsum for lane's 4 k

    for (int pos = start; pos < end; pos++) {
        int2 es = g_es[pos];
        float4 hd4 = *(const float4*)(g_hid + (size_t)es.x * 128 + 4*l);
        const ulonglong2* hjp = (const ulonglong2*)(hin + (size_t)es.y * 16);
        ulonglong2 ha = hjp[0], hb = hjp[1];
        ull hv[8] = {ha.x, ha.y, hb.x, hb.y, 0, 0, 0, 0};
        ulonglong2 hc = ((const ulonglong2*)(hin + (size_t)es.y * 16))[2];
        ulonglong2 hdq = ((const ulonglong2*)(hin + (size_t)es.y * 16))[3];
        hv[4] = hc.x; hv[5] = hc.y; hv[6] = hdq.x; hv[7] = hdq.y;
#pragma unroll
        for (int q = 0; q < 8; q++) Hs[q] = add2(Hs[q], hv[q]);
        hs0 += hd4.x; hs1 += hd4.y; hs2 += hd4.z; hs3 += hd4.w;
        ull p0 = pack2(hd4.x, hd4.x), p1 = pack2(hd4.y, hd4.y);
        ull p2 = pack2(hd4.z, hd4.z), p3 = pack2(hd4.w, hd4.w);
#pragma unroll
        for (int q = 0; q < 8; q++) {
            T[0][q] = fma2(p0, hv[q], T[0][q]);
            T[1][q] = fma2(p1, hv[q], T[1][q]);
            T[2][q] = fma2(p2, hv[q], T[2][q]);
            T[3][q] = fma2(p3, hv[q], T[3][q]);
        }
    }

    float* Srow = g_S + (size_t)n * KDIM;
    float hn = (l < 16) ? hin[(size_t)n * 16 + l] : 0.f;
    float hval[16];
#pragma unroll
    for (int r = 0; r < 16; r++) hval[r] = __shfl_sync(0xffffffffu, hn, r);

    // T rows: S[(4l+kk)*16 + j]
#pragma unroll
    for (int kk = 0; kk < 4; kk++) {
        float t[16];
#pragma unroll
        for (int q = 0; q < 8; q++) unpack2(T[kk][q], t[2*q], t[2*q+1]);
        float4* dT = (float4*)(Srow + (size_t)(4*l + kk) * 16);
        dT[0] = make_float4(t[0], t[1], t[2], t[3]);
        dT[1] = make_float4(t[4], t[5], t[6], t[7]);
        dT[2] = make_float4(t[8], t[9], t[10], t[11]);
        dT[3] = make_float4(t[12], t[13], t[14], t[15]);
    }
    // Hsum ⊗ h rows: S[2048 + (4l+kk)*16 + r]
    float hsv[4] = {hs0, hs1, hs2, hs3};
#pragma unroll
    for (int kk = 0; kk < 4; kk++) {
        float hs = hsv[kk];
        float4* dU = (float4*)(Srow + 2048 + (size_t)(4*l + kk) * 16);
        dU[0] = make_float4(hs*hval[0],  hs*hval[1],  hs*hval[2],  hs*hval[3]);
        dU[1] = make_float4(hs*hval[4],  hs*hval[5],  hs*hval[6],  hs*hval[7]);
        dU[2] = make_float4(hs*hval[8],  hs*hval[9],  hs*hval[10], hs*hval[11]);
        dU[3] = make_float4(hs*hval[12], hs*hval[13], hs*hval[14], hs*hval[15]);
    }
    // tail columns
    float dg = (float)(end - start);
    if (l < 16) {
        Srow[4096 + l] = dg * hn;          // pairs with b2 dst rows
        Srow[4128 + l] = hn;               // pairs with root rows
        Srow[4144 + l] = 0.f;              // pad
    }
    if (l == 0) {
#pragma unroll
        for (int q = 0; q < 8; q++) {
            float a, b; unpack2(Hs[q], a, b);
            Srow[4112 + 2*q]     = a;      // pairs with b2 src rows
            Srow[4112 + 2*q + 1] = b;
        }
    }
}

// ---------------- GEMM: hout += S @ B (8-way K-split, atomicAdd) -------------
#define GT 256
#define SA_P 129
__global__ void __launch_bounds__(GT) k_gemm(int layer, int sout, float* ext) {
    __shared__ __align__(16) float sA[64 * SA_P];
    __shared__ __align__(16) float sB[64 * 16];
    float* hout = pick_buf(sout, ext);
    const float* B = g_B[layer];
    int tid = threadIdx.x;
    int n0 = blockIdx.x * 128;
    int ks = blockIdx.y;                  // 0..7 over 65 chunks: 9 + 7*8
    int c0 = (ks == 0) ? 0 : 9 + (ks - 1) * 8;
    int nc = (ks == 0) ? 9 : 8;
    int nn = tid & 127, half = tid >> 7;
    ull acc[4] = {0ull, 0ull, 0ull, 0ull};

    for (int ci = 0; ci < nc; ci++) {
        int k0 = (c0 + ci) * 64;
        __syncthreads();
        ((float4*)sB)[tid] = ((const float4*)(B + (size_t)k0 * 16))[tid];
        for (int i = tid; i < 2048; i += GT) {
            int an = i >> 4, q = i & 15;
            float4 v = make_float4(0.f, 0.f, 0.f, 0.f);
            if (n0 + an < N_NODES)
                v = *(const float4*)(g_S + (size_t)(n0 + an) * KDIM + k0 + 4*q);
            sA[(4*q + 0) * SA_P + an] = v.x;
            sA[(4*q + 1) * SA_P + an] = v.y;
            sA[(4*q + 2) * SA_P + an] = v.z;
            sA[(4*q + 3) * SA_P + an] = v.w;
        }
        __syncthreads();
#pragma unroll 8
        for (int k = 0; k < 64; k++) {
            float a = sA[k * SA_P + nn];
            ull a2 = pack2(a, a);
            ulonglong2 b01 = *(const ulonglong2*)&sB[k * 16 + 8 * half];
            ulonglong2 b23 = *(const ulonglong2*)&sB[k * 16 + 8 * half + 4];
            acc[0] = fma2(a2, b01.x, acc[0]);
            acc[1] = fma2(a2, b01.y, acc[1]);
            acc[2] = fma2(a2, b23.x, acc[2]);
            acc[3] = fma2(a2, b23.y, acc[3]);
        }
    }

    int n = n0 + nn;
    if (n < N_NODES) {
        float o[8];
        unpack2(acc[0], o[0], o[1]);
        unpack2(acc[1], o[2], o[3]);
        unpack2(acc[2], o[4], o[5]);
        unpack2(acc[3], o[6], o[7]);
        float* dst = hout + (size_t)n * 16 + 8 * half;
#pragma unroll
        for (int j = 0; j < 8; j++) atomicAdd(dst + j, o[j]);
    }
}

// ---------------- edge embedding + log_softmax --------------------------------
__global__ void k_edge_embed(const float* __restrict__ ea,
                             const float* __restrict__ We,
                             const float* __restrict__ be,
                             float* __restrict__ ee_out,
                             float* __restrict__ lsm_out,
                             int n_ee, int n_lsm) {
    __shared__ float sW[256];
    __shared__ float sb[16];
    int tid = threadIdx.x;
    if (tid < 256) sW[tid] = We[tid];
    if (tid < 16) sb[tid] = be[tid];
    __syncthreads();
    int e = blockIdx.x * blockDim.x + tid;
    if (e >= N_EDGES) return;
    float xi[16];
    const float4* xp = (const float4*)(ea + (size_t)e * 16);
#pragma unroll
    for (int q = 0; q < 4; q++) {
        float4 v = xp[q];
        xi[4*q] = v.x; xi[4*q+1] = v.y; xi[4*q+2] = v.z; xi[4*q+3] = v.w;
    }
    float v[16];
    float m = -1e30f;
#pragma unroll
    for (int d = 0; d < 16; d++) {
        float acc = sb[d];
#pragma unroll
        for (int k = 0; k < 16; k++) acc = fmaf(xi[k], sW[k*16+d], acc);
        v[d] = fmaxf(acc, 0.f);
        m = fmaxf(m, v[d]);
    }
    float s = 0.f;
#pragma unroll
    for (int d = 0; d < 16; d++) s += expf(v[d] - m);
    float ls = m + logf(s);
    if (e < n_ee) {
        float4* eo = (float4*)(ee_out + (size_t)e * 16);
#pragma unroll
        for (int q = 0; q < 4; q++)
            eo[q] = make_float4(v[4*q], v[4*q+1], v[4*q+2], v[4*q+3]);
    }
    if (e < n_lsm) {
        float4* lo = (float4*)(lsm_out + (size_t)e * 16);
#pragma unroll
        for (int q = 0; q < 4; q++)
            lo[q] = make_float4(v[4*q] - ls, v[4*q+1] - ls, v[4*q+2] - ls, v[4*q+3] - ls);
    }
}

// ---------------- edge_index passthrough --------------------------------------
__global__ void k_ei_copy(const int* __restrict__ ei, float* __restrict__ out,
                          int n_vals) {
    int i = blockIdx.x * blockDim.x + threadIdx.x;
    if (i < n_vals) out[i] = (float)ei[i];
}

// ---------------- launch -------------------------------------------------------
extern "C" void kernel_launch(void* const* d_in, const int* in_sizes, int n_in,
                              void* d_out, int out_size) {
    const float* x     = (const float*)d_in[0];
    const int*   ei    = (const int*)d_in[1];
    const float* ea    = (const float*)d_in[2];
    const float* Wn    = (const float*)d_in[3];
    const float* bn    = (const float*)d_in[4];
    const float* We    = (const float*)d_in[5];
    const float* be    = (const float*)d_in[6];
    const float* W1    = (const float*)d_in[7];
    const float* b1    = (const float*)d_in[8];
    const float* W2    = (const float*)d_in[9];
    const float* b2    = (const float*)d_in[10];
    const float* root1 = (const float*)d_in[11];
    const float* bias1 = (const float*)d_in[12];
    const float* root2 = (const float*)d_in[13];
    const float* bias2 = (const float*)d_in[14];

    float* out = (float*)d_out;
    size_t cap = (size_t)out_size;

    size_t ei_slots = (cap == 13120000) ? 0 : 2ull * N_EDGES;
    size_t off_h   = 0;
    size_t off_ei  = off_h + (size_t)N_NODES * 16;
    size_t off_ee  = off_ei + ei_slots;
    size_t off_lsm = off_ee + (size_t)N_EDGES * 16;
    auto avail = [&](size_t off) -> size_t { return off < cap ? cap - off : 0; };

    float* out_h   = out + off_h;
    float* out_ei  = out + off_ei;
    float* out_ee  = out + off_ee;
    float* out_lsm = out + off_lsm;

    bool h_fits = avail(off_h) >= (size_t)N_NODES * 16;
    int  n_ei   = ei_slots ? (int)min((size_t)(2 * N_EDGES), avail(off_ei)) : 0;
    int  n_ee   = (int)min((size_t)N_EDGES, avail(off_ee) / 16);
    int  n_lsm  = (int)min((size_t)N_EDGES, avail(off_lsm) / 16);
    int  sout2  = h_fits ? 2 : 0;

    // 0: degree count + node embedding
    k_count_embed<<<COUNT_BLOCKS + 79, 256>>>(ei, x, Wn, bn);
    // 1: prefix scan (re-zeros g_cursor)
    k_scan<<<1, 1024>>>();
    // 2: fill edge list + hid GEMM + B/bias init
    k_prep<<<COUNT_BLOCKS + HID_BLOCKS + INIT_BLOCKS, 256>>>(
        ei, ea, W1, b1, W2, b2, root1, root2, bias1, bias2, sout2, out_h);
    // 3: edge pass layer 1 (profiled)
    k_edge_pass<<<N_NODES / 8, 256>>>(0);
    // 4: GEMM layer 1 -> g_h1 (+= over bias1 seed)
    dim3 gg((N_NODES + 127) / 128, 8);
    k_gemm<<<gg, GT>>>(0, 1, out_h);
    // 5: edge pass layer 2
    k_edge_pass<<<N_NODES / 8, 256>>>(1);
    // 6: GEMM layer 2 -> out_h (+= over bias2 seed)
    k_gemm<<<gg, GT>>>(1, sout2, out_h);
    // 7: edge embedding + log_softmax
    if (n_ee > 0 || n_lsm > 0)
        k_edge_embed<<<(N_EDGES + 255) / 256, 256>>>(ea, We, be, out_ee, out_lsm,
                                                     n_ee, n_lsm);
    // 8: edge_index passthrough
    if (n_ei > 0)
        k_ei_copy<<<(n_ei + 255) / 256, 256>>>(ei, out_ei, n_ei);
}

// round 10
// speedup vs baseline: 1.0746x; 1.0746x over previous
#include <cuda_runtime.h>
#include <math.h>

#define N_NODES 20000
#define N_EDGES 400000
#define KT 2048                    // T columns per node
typedef unsigned long long ull;

// ---------------- device globals --------------------------------------------
__device__ float g_S[(size_t)N_NODES * KT];      // T matrix only (164 MB)
__device__ float g_Hsum[(size_t)N_NODES * 128];  // per-node hid sums
__device__ float g_HsJ[N_NODES * 16];            // per-node sum of h[src]
__device__ float g_hid[(size_t)N_EDGES * 128];   // relu(ea@W1+b1), layer-shared
__device__ float g_B[4096 * 16];                 // permuted W2 (layer-indep)
__device__ float g_h0[N_NODES * 16];
__device__ float g_h1[N_NODES * 16];
__device__ int   g_deg[N_NODES];
__device__ int   g_cursor[N_NODES];
__device__ int   g_off[N_NODES + 1];
__device__ int2  g_es[N_EDGES];                  // (edge id, src) sorted by dst

__device__ __forceinline__ float* pick_buf(int s, float* ext) {
    if (s == 0) return g_h0;
    if (s == 1) return g_h1;
    return ext;
}
__device__ __forceinline__ const float* pick_cbuf(int s, const float* ext) {
    if (s == 0) return g_h0;
    if (s == 1) return g_h1;
    return ext;
}

// ---------------- f32x2 helpers ----------------------------------------------
__device__ __forceinline__ ull pack2(float a, float b) {
    ull r; asm("mov.b64 %0, {%1, %2};" : "=l"(r) : "f"(a), "f"(b)); return r;
}
__device__ __forceinline__ void unpack2(ull v, float& a, float& b) {
    asm("mov.b64 {%0, %1}, %2;" : "=f"(a), "=f"(b) : "l"(v));
}
__device__ __forceinline__ ull fma2(ull a, ull b, ull c) {
    ull d; asm("fma.rn.f32x2 %0, %1, %2, %3;" : "=l"(d) : "l"(a), "l"(b), "l"(c));
    return d;
}
__device__ __forceinline__ ull add2(ull a, ull b) {
    ull d; asm("add.rn.f32x2 %0, %1, %2;" : "=l"(d) : "l"(a), "l"(b)); return d;
}

// ---------------- launch 0: degree count + node embedding --------------------
#define COUNT_BLOCKS 1563
__global__ void k_count_embed(const int* __restrict__ ei,
                              const float* __restrict__ x,
                              const float* __restrict__ Wn,
                              const float* __restrict__ bn) {
    int b = blockIdx.x;
    if (b < COUNT_BLOCKS) {
        int e = b * 256 + threadIdx.x;
        if (e < N_EDGES) atomicAdd(&g_deg[ei[N_EDGES + e]], 1);
    } else {
        __shared__ float sW[256];
        __shared__ float sb[16];
        int tid = threadIdx.x;
        sW[tid] = Wn[tid];
        if (tid < 16) sb[tid] = bn[tid];
        __syncthreads();
        int n = (b - COUNT_BLOCKS) * 256 + tid;
        if (n >= N_NODES) return;
        float xi[16];
        const float4* xp = (const float4*)(x + (size_t)n * 16);
#pragma unroll
        for (int q = 0; q < 4; q++) {
            float4 v = xp[q];
            xi[4*q] = v.x; xi[4*q+1] = v.y; xi[4*q+2] = v.z; xi[4*q+3] = v.w;
        }
        float o[16];
#pragma unroll
        for (int d = 0; d < 16; d++) {
            float acc = sb[d];
#pragma unroll
            for (int k = 0; k < 16; k++) acc = fmaf(xi[k], sW[k*16+d], acc);
            o[d] = fmaxf(acc, 0.f);
        }
        float4* op = (float4*)(g_h0 + (size_t)n * 16);
#pragma unroll
        for (int q = 0; q < 4; q++)
            op[q] = make_float4(o[4*q], o[4*q+1], o[4*q+2], o[4*q+3]);
    }
}

// ---------------- launch 1: prefix scan --------------------------------------
__global__ void __launch_bounds__(1024) k_scan() {
    __shared__ int sm[1024];
    int t = threadIdx.x;
    int base = t * 20;
    int vals[20];
    int local = 0;
#pragma unroll
    for (int i = 0; i < 20; i++) {
        int idx = base + i;
        vals[i] = (idx < N_NODES) ? g_deg[idx] : 0;
        local += vals[i];
    }
    sm[t] = local;
    __syncthreads();
    for (int off = 1; off < 1024; off <<= 1) {
        int v = (t >= off) ? sm[t - off] : 0;
        __syncthreads();
        sm[t] += v;
        __syncthreads();
    }
    int run = sm[t] - local;
#pragma unroll
    for (int i = 0; i < 20; i++) {
        int idx = base + i;
        if (idx < N_NODES) { g_off[idx] = run; run += vals[i]; g_cursor[idx] = 0; }
    }
    if (t == 0) g_off[N_NODES] = N_EDGES;
}

// ---------------- launch 2: fused fill + hid + B build -----------------------
#define HID_BLOCKS 6250
#define B_BLOCKS 256                         // 4096*16/256
__global__ void __launch_bounds__(256) k_prep(
    const int* __restrict__ ei, const float* __restrict__ ea,
    const float* __restrict__ W1, const float* __restrict__ b1,
    const float* __restrict__ W2) {
    int b = blockIdx.x;
    int tid = threadIdx.x;
    if (b < COUNT_BLOCKS) {
        int e = b * 256 + tid;
        if (e < N_EDGES) {
            int d = ei[N_EDGES + e];
            int pos = g_off[d] + atomicAdd(&g_cursor[d], 1);
            g_es[pos] = make_int2(e, ei[e]);
        }
        if (e < N_NODES) g_deg[e] = 0;
    } else if (b < COUNT_BLOCKS + HID_BLOCKS) {
        __shared__ float sEA[64 * 17];
        __shared__ float sW1[16 * 128];
        __shared__ float sB1[128];
        int e0 = (b - COUNT_BLOCKS) * 64;
        for (int idx = tid; idx < 64 * 16; idx += 256) {
            int e = idx >> 4, k = idx & 15;
            sEA[e*17 + k] = ea[(size_t)(e0 + e)*16 + k];
        }
        for (int idx = tid; idx < 2048; idx += 256) sW1[idx] = W1[idx];
        if (tid < 128) sB1[tid] = b1[tid];
        __syncthreads();
        int el = tid >> 2;
        int p  = tid & 3;
        float a[16];
#pragma unroll
        for (int k = 0; k < 16; k++) a[k] = sEA[el*17 + k];
        float* outp = g_hid + (size_t)(e0 + el) * 128 + p * 32;
#pragma unroll
        for (int uu = 0; uu < 32; uu += 4) {
            int ub = p*32 + uu;
            float c0 = sB1[ub+0], c1 = sB1[ub+1], c2 = sB1[ub+2], c3 = sB1[ub+3];
#pragma unroll
            for (int k = 0; k < 16; k++) {
                float av = a[k];
                const float* wr = &sW1[k*128 + ub];
                c0 = fmaf(av, wr[0], c0);
                c1 = fmaf(av, wr[1], c1);
                c2 = fmaf(av, wr[2], c2);
                c3 = fmaf(av, wr[3], c3);
            }
            *(float4*)(outp + uu) = make_float4(fmaxf(c0, 0.f), fmaxf(c1, 0.f),
                                                fmaxf(c2, 0.f), fmaxf(c3, 0.f));
        }
    } else {
        // B: rows 0..2047 -> W2[k][(16+j)*16+d]; rows 2048..4095 -> W2[k][r*16+d]
        int idx = (b - COUNT_BLOCKS - HID_BLOCKS) * 256 + tid;
        int kj = idx >> 4, d = idx & 15;
        float v;
        if (kj < 2048) {
            int k = kj >> 4, j = kj & 15;
            v = W2[(size_t)k * 512 + (16 + j) * 16 + d];
        } else {
            int m = kj - 2048;
            int k = m >> 4, r = m & 15;
            v = W2[(size_t)k * 512 + r * 16 + d];
        }
        g_B[idx] = v;
    }
}

// ---------------- edge pass: 1 warp/node, pipelined, T+Hsum+Hs out -----------
#define EP_SMEM (8 * 32 * 68 * 4)            // 69632 B (warp-local transpose)
__global__ void __launch_bounds__(256, 2) k_edge_pass(int sin) {
    extern __shared__ float st[];
    const float* hin = (sin == 0) ? g_h0 : g_h1;
    int tid = threadIdx.x, wid = tid >> 5, l = tid & 31;
    int n = blockIdx.x * 8 + wid;

    int start = g_off[n], end = g_off[n + 1];

    ull T[4][8];
#pragma unroll
    for (int kk = 0; kk < 4; kk++)
#pragma unroll
        for (int q = 0; q < 8; q++) T[kk][q] = 0ull;
    ull Hs[8];
#pragma unroll
    for (int q = 0; q < 8; q++) Hs[q] = 0ull;
    float hs0 = 0.f, hs1 = 0.f, hs2 = 0.f, hs3 = 0.f;

    if (start < end) {
        int last = end - 1;
        int2 esC = g_es[start];
        // data for current iteration
        float4 hidN = *(const float4*)(g_hid + (size_t)esC.x * 128 + 4*l);
        const ulonglong2* hp = (const ulonglong2*)(hin + (size_t)esC.y * 16);
        ulonglong2 ha = hp[0], hb = hp[1], hc = hp[2], hd = hp[3];
        ull hN[8] = {ha.x, ha.y, hb.x, hb.y, hc.x, hc.y, hd.x, hd.y};
        // index for iteration +1
        int p1 = start + 1 <= last ? start + 1 : last;
        int2 esF = g_es[p1];

        for (int pos = start; pos < end; pos++) {
            // current data
            float4 hd4 = hidN;
            ull hv[8];
#pragma unroll
            for (int q = 0; q < 8; q++) hv[q] = hN[q];
            // prefetch index for pos+2
            int p2 = pos + 2 <= last ? pos + 2 : last;
            int2 esF2 = g_es[p2];
            // issue loads for pos+1 (esF)
            hidN = *(const float4*)(g_hid + (size_t)esF.x * 128 + 4*l);
            const ulonglong2* hp2 = (const ulonglong2*)(hin + (size_t)esF.y * 16);
            ulonglong2 na = hp2[0], nb = hp2[1], nc = hp2[2], nd = hp2[3];
            hN[0] = na.x; hN[1] = na.y; hN[2] = nb.x; hN[3] = nb.y;
            hN[4] = nc.x; hN[5] = nc.y; hN[6] = nd.x; hN[7] = nd.y;
            esF = esF2;
            // compute with current
#pragma unroll
            for (int q = 0; q < 8; q++) Hs[q] = add2(Hs[q], hv[q]);
            hs0 += hd4.x; hs1 += hd4.y; hs2 += hd4.z; hs3 += hd4.w;
            ull p0 = pack2(hd4.x, hd4.x), pq1 = pack2(hd4.y, hd4.y);
            ull pq2 = pack2(hd4.z, hd4.z), pq3 = pack2(hd4.w, hd4.w);
#pragma unroll
            for (int q = 0; q < 8; q++) {
                T[0][q] = fma2(p0, hv[q], T[0][q]);
                T[1][q] = fma2(pq1, hv[q], T[1][q]);
                T[2][q] = fma2(pq2, hv[q], T[2][q]);
                T[3][q] = fma2(pq3, hv[q], T[3][q]);
            }
        }
    }

    // ---- write T via warp-local smem transpose (coalesced global stores) ----
    float* W = st + wid * (32 * 68) + l * 68;
#pragma unroll
    for (int kk = 0; kk < 4; kk++) {
        float t[16];
#pragma unroll
        for (int q = 0; q < 8; q++) unpack2(T[kk][q], t[2*q], t[2*q+1]);
#pragma unroll
        for (int f = 0; f < 4; f++)
            *(float4*)&W[kk*16 + 4*f] = make_float4(t[4*f], t[4*f+1], t[4*f+2], t[4*f+3]);
    }
    __syncwarp();
    float* Wbase = st + wid * (32 * 68);
    float* Trow = g_S + (size_t)n * KT;
#pragma unroll
    for (int s = 0; s < 16; s++) {
        int idx = s * 128 + 4 * l;
        float4 v = *(float4*)&Wbase[(idx >> 6) * 68 + (idx & 63)];
        *(float4*)&Trow[idx] = v;
    }
    // Hsum (coalesced float4) and Hs (lane 0)
    *(float4*)&g_Hsum[(size_t)n * 128 + 4*l] = make_float4(hs0, hs1, hs2, hs3);
    if (l == 0) {
#pragma unroll
        for (int q = 0; q < 8; q++) {
            float a, b; unpack2(Hs[q], a, b);
            g_HsJ[n * 16 + 2*q]     = a;
            g_HsJ[n * 16 + 2*q + 1] = b;
        }
    }
}

// ---------------- epilogue: seed hout with non-GEMM terms --------------------
__global__ void k_epi(int sin, int sout, float* ext,
                      const float* __restrict__ root,
                      const float* __restrict__ b2,
                      const float* __restrict__ bias) {
    __shared__ float sR[256];
    __shared__ float sB2[512];
    __shared__ float sBi[16];
    const float* hin = pick_cbuf(sin, ext);
    float* hout = pick_buf(sout, ext);
    int tid = threadIdx.x;
    sR[tid] = root[tid];
    sB2[tid] = b2[tid];
    sB2[256 + tid] = b2[256 + tid];
    if (tid < 16) sBi[tid] = bias[tid];
    __syncthreads();
    int n = blockIdx.x * 256 + tid;
    if (n >= N_NODES) return;
    float h[16], hs[16];
    const float4* hp = (const float4*)(hin + (size_t)n * 16);
    const float4* sp = (const float4*)(g_HsJ + (size_t)n * 16);
#pragma unroll
    for (int q = 0; q < 4; q++) {
        float4 a = hp[q]; h[4*q] = a.x; h[4*q+1] = a.y; h[4*q+2] = a.z; h[4*q+3] = a.w;
        float4 b = sp[q]; hs[4*q] = b.x; hs[4*q+1] = b.y; hs[4*q+2] = b.z; hs[4*q+3] = b.w;
    }
    float dg = (float)(g_off[n+1] - g_off[n]);
    float o[16];
#pragma unroll
    for (int d = 0; d < 16; d++) o[d] = sBi[d];
#pragma unroll
    for (int r = 0; r < 16; r++) {
        float hr = h[r], hdg = h[r] * dg, hj = hs[r];
#pragma unroll
        for (int d = 0; d < 16; d++) {
            o[d] = fmaf(hr, sR[r*16+d], o[d]);
            o[d] = fmaf(hdg, sB2[r*16+d], o[d]);
            o[d] = fmaf(hj, sB2[256 + r*16+d], o[d]);
        }
    }
    float4* op = (float4*)(hout + (size_t)n * 16);
#pragma unroll
    for (int q = 0; q < 4; q++)
        op[q] = make_float4(o[4*q], o[4*q+1], o[4*q+2], o[4*q+3]);
}

// ---------------- GEMM: hout += [T | synth(Hsum⊗h)] @ B (8-way K-split) ------
#define GT 256
#define SA_P 129
__global__ void __launch_bounds__(GT) k_gemm(int sin, int sout, float* ext) {
    __shared__ __align__(16) float sA[64 * SA_P];
    __shared__ __align__(16) float sB[64 * 16];
    const float* hin = pick_cbuf(sin, ext);
    float* hout = pick_buf(sout, ext);
    int tid = threadIdx.x;
    int n0 = blockIdx.x * 128;
    int ks = blockIdx.y;                  // 0..7, 8 chunks each (64 total)
    int nn = tid & 127, half = tid >> 7;
    ull acc[4] = {0ull, 0ull, 0ull, 0ull};

    for (int ci = 0; ci < 8; ci++) {
        int c = ks * 8 + ci;
        int k0 = c * 64;
        __syncthreads();
        ((float4*)sB)[tid] = ((const float4*)(g_B + (size_t)k0 * 16))[tid];
        for (int i = tid; i < 2048; i += GT) {
            int an = i >> 4, q = i & 15;
            int gn = n0 + an;
            float4 v = make_float4(0.f, 0.f, 0.f, 0.f);
            if (gn < N_NODES) {
                if (c < 32) {
                    v = *(const float4*)(g_S + (size_t)gn * KT + k0 + 4*q);
                } else {
                    int m = k0 - 2048 + 4*q;
                    float hsv = g_Hsum[(size_t)gn * 128 + (m >> 4)];
                    float4 h4 = ((const float4*)(hin + (size_t)gn * 16))[(m & 15) >> 2];
                    v = make_float4(hsv*h4.x, hsv*h4.y, hsv*h4.z, hsv*h4.w);
                }
            }
            sA[(4*q + 0) * SA_P + an] = v.x;
            sA[(4*q + 1) * SA_P + an] = v.y;
            sA[(4*q + 2) * SA_P + an] = v.z;
            sA[(4*q + 3) * SA_P + an] = v.w;
        }
        __syncthreads();
#pragma unroll 8
        for (int k = 0; k < 64; k++) {
            float a = sA[k * SA_P + nn];
            ull a2 = pack2(a, a);
            ulonglong2 b01 = *(const ulonglong2*)&sB[k * 16 + 8 * half];
            ulonglong2 b23 = *(const ulonglong2*)&sB[k * 16 + 8 * half + 4];
            acc[0] = fma2(a2, b01.x, acc[0]);
            acc[1] = fma2(a2, b01.y, acc[1]);
            acc[2] = fma2(a2, b23.x, acc[2]);
            acc[3] = fma2(a2, b23.y, acc[3]);
        }
    }

    int n = n0 + nn;
    if (n < N_NODES) {
        float o[8];
        unpack2(acc[0], o[0], o[1]);
        unpack2(acc[1], o[2], o[3]);
        unpack2(acc[2], o[4], o[5]);
        unpack2(acc[3], o[6], o[7]);
        float* dst = hout + (size_t)n * 16 + 8 * half;
#pragma unroll
        for (int j = 0; j < 8; j++) atomicAdd(dst + j, o[j]);
    }
}

// ---------------- edge embedding + log_softmax --------------------------------
__global__ void k_edge_embed(const float* __restrict__ ea,
                             const float* __restrict__ We,
                             const float* __restrict__ be,
                             float* __restrict__ ee_out,
                             float* __restrict__ lsm_out,
                             int n_ee, int n_lsm) {
    __shared__ float sW[256];
    __shared__ float sb[16];
    int tid = threadIdx.x;
    if (tid < 256) sW[tid] = We[tid];
    if (tid < 16) sb[tid] = be[tid];
    __syncthreads();
    int e = blockIdx.x * blockDim.x + tid;
    if (e >= N_EDGES) return;
    float xi[16];
    const float4* xp = (const float4*)(ea + (size_t)e * 16);
#pragma unroll
    for (int q = 0; q < 4; q++) {
        float4 v = xp[q];
        xi[4*q] = v.x; xi[4*q+1] = v.y; xi[4*q+2] = v.z; xi[4*q+3] = v.w;
    }
    float v[16];
    float m = -1e30f;
#pragma unroll
    for (int d = 0; d < 16; d++) {
        float acc = sb[d];
#pragma unroll
        for (int k = 0; k < 16; k++) acc = fmaf(xi[k], sW[k*16+d], acc);
        v[d] = fmaxf(acc, 0.f);
        m = fmaxf(m, v[d]);
    }
    float s = 0.f;
#pragma unroll
    for (int d = 0; d < 16; d++) s += expf(v[d] - m);
    float ls = m + logf(s);
    if (e < n_ee) {
        float4* eo = (float4*)(ee_out + (size_t)e * 16);
#pragma unroll
        for (int q = 0; q < 4; q++)
            eo[q] = make_float4(v[4*q], v[4*q+1], v[4*q+2], v[4*q+3]);
    }
    if (e < n_lsm) {
        float4* lo = (float4*)(lsm_out + (size_t)e * 16);
#pragma unroll
        for (int q = 0; q < 4; q++)
            lo[q] = make_float4(v[4*q] - ls, v[4*q+1] - ls, v[4*q+2] - ls, v[4*q+3] - ls);
    }
}

// ---------------- edge_index passthrough --------------------------------------
__global__ void k_ei_copy(const int* __restrict__ ei, float* __restrict__ out,
                          int n_vals) {
    int i = blockIdx.x * blockDim.x + threadIdx.x;
    if (i < n_vals) out[i] = (float)ei[i];
}

// ---------------- launch -------------------------------------------------------
extern "C" void kernel_launch(void* const* d_in, const int* in_sizes, int n_in,
                              void* d_out, int out_size) {
    const float* x     = (const float*)d_in[0];
    const int*   ei    = (const int*)d_in[1];
    const float* ea    = (const float*)d_in[2];
    const float* Wn    = (const float*)d_in[3];
    const float* bn    = (const float*)d_in[4];
    const float* We    = (const float*)d_in[5];
    const float* be    = (const float*)d_in[6];
    const float* W1    = (const float*)d_in[7];
    const float* b1    = (const float*)d_in[8];
    const float* W2    = (const float*)d_in[9];
    const float* b2    = (const float*)d_in[10];
    const float* root1 = (const float*)d_in[11];
    const float* bias1 = (const float*)d_in[12];
    const float* root2 = (const float*)d_in[13];
    const float* bias2 = (const float*)d_in[14];

    float* out = (float*)d_out;
    size_t cap = (size_t)out_size;

    size_t ei_slots = (cap == 13120000) ? 0 : 2ull * N_EDGES;
    size_t off_h   = 0;
    size_t off_ei  = off_h + (size_t)N_NODES * 16;
    size_t off_ee  = off_ei + ei_slots;
    size_t off_lsm = off_ee + (size_t)N_EDGES * 16;
    auto avail = [&](size_t off) -> size_t { return off < cap ? cap - off : 0; };

    float* out_h   = out + off_h;
    float* out_ei  = out + off_ei;
    float* out_ee  = out + off_ee;
    float* out_lsm = out + off_lsm;

    bool h_fits = avail(off_h) >= (size_t)N_NODES * 16;
    int  n_ei   = ei_slots ? (int)min((size_t)(2 * N_EDGES), avail(off_ei)) : 0;
    int  n_ee   = (int)min((size_t)N_EDGES, avail(off_ee) / 16);
    int  n_lsm  = (int)min((size_t)N_EDGES, avail(off_lsm) / 16);
    int  sout2  = h_fits ? 2 : 0;

    cudaFuncSetAttribute(k_edge_pass, cudaFuncAttributeMaxDynamicSharedMemorySize,
                         EP_SMEM);

    // 0: degree count + node embedding
    k_count_embed<<<COUNT_BLOCKS + 79, 256>>>(ei, x, Wn, bn);
    // 1: prefix scan (re-zeros g_cursor)
    k_scan<<<1, 1024>>>();
    // 2: fill edge list + hid GEMM + B build
    k_prep<<<COUNT_BLOCKS + HID_BLOCKS + B_BLOCKS, 256>>>(ei, ea, W1, b1, W2);

    dim3 gg((N_NODES + 127) / 128, 8);
    // 3: edge pass layer 1 (profiled)
    k_edge_pass<<<N_NODES / 8, 256, EP_SMEM>>>(0);
    // 4: epilogue seeds g_h1
    k_epi<<<(N_NODES + 255) / 256, 256>>>(0, 1, out_h, root1, b2, bias1);
    // 5: GEMM layer 1 accumulates into g_h1
    k_gemm<<<gg, GT>>>(0, 1, out_h);
    // 6-8: layer 2
    k_edge_pass<<<N_NODES / 8, 256, EP_SMEM>>>(1);
    k_epi<<<(N_NODES + 255) / 256, 256>>>(1, sout2, out_h, root2, b2, bias2);
    k_gemm<<<gg, GT>>>(1, sout2, out_h);

    // 9: edge embedding + log_softmax
    if (n_ee > 0 || n_lsm > 0)
        k_edge_embed<<<(N_EDGES + 255) / 256, 256>>>(ea, We, be, out_ee, out_lsm,
                                                     n_ee, n_lsm);
    // 10: edge_index passthrough
    if (n_ei > 0)
        k_ei_copy<<<(n_ei + 255) / 256, 256>>>(ei, out_ei, n_ei);
}

// round 11
// speedup vs baseline: 1.0901x; 1.0144x over previous
#include <cuda_runtime.h>
#include <math.h>

#define N_NODES 20000
#define N_EDGES 400000
#define KT 2048
typedef unsigned long long ull;

// ---------------- device globals --------------------------------------------
__device__ float g_S[(size_t)N_NODES * KT];      // per-node T rows
__device__ float g_Hsum[(size_t)N_NODES * 128];  // per-node hid sums
__device__ float g_HsJ[N_NODES * 16];            // per-node sum of h[src]
__device__ float g_hid[(size_t)N_EDGES * 128];   // hid in DST-SORTED order
__device__ float g_B[4096 * 16];                 // permuted W2
__device__ float g_h0[N_NODES * 16];
__device__ float g_h1[N_NODES * 16];
__device__ int   g_deg[N_NODES];
__device__ int   g_cursor[N_NODES];
__device__ int   g_off[N_NODES + 1];
__device__ int   g_pos[N_EDGES];                 // original e -> sorted pos
__device__ int2  g_es[N_EDGES];                  // (edge id, src) sorted by dst

__device__ __forceinline__ float* pick_buf(int s, float* ext) {
    if (s == 0) return g_h0;
    if (s == 1) return g_h1;
    return ext;
}
__device__ __forceinline__ const float* pick_cbuf(int s, const float* ext) {
    if (s == 0) return g_h0;
    if (s == 1) return g_h1;
    return ext;
}

// ---------------- f32x2 helpers ----------------------------------------------
__device__ __forceinline__ ull pack2(float a, float b) {
    ull r; asm("mov.b64 %0, {%1, %2};" : "=l"(r) : "f"(a), "f"(b)); return r;
}
__device__ __forceinline__ void unpack2(ull v, float& a, float& b) {
    asm("mov.b64 {%0, %1}, %2;" : "=f"(a), "=f"(b) : "l"(v));
}
__device__ __forceinline__ ull fma2(ull a, ull b, ull c) {
    ull d; asm("fma.rn.f32x2 %0, %1, %2, %3;" : "=l"(d) : "l"(a), "l"(b), "l"(c));
    return d;
}
__device__ __forceinline__ ull add2(ull a, ull b) {
    ull d; asm("add.rn.f32x2 %0, %1, %2;" : "=l"(d) : "l"(a), "l"(b)); return d;
}

// ---------------- launch 0: fused front (count/embed/edge-embed/ei) ----------
#define COUNT_BLOCKS 1563
#define EMBED_BLOCKS 79
#define EE_BLOCKS 1563
#define EIC_BLOCKS 3125
#define FRONT_BLOCKS (COUNT_BLOCKS + EMBED_BLOCKS + EE_BLOCKS + EIC_BLOCKS)

__global__ void __launch_bounds__(256) k_front(
    const int* __restrict__ ei, const float* __restrict__ x,
    const float* __restrict__ Wn, const float* __restrict__ bn,
    const float* __restrict__ ea, const float* __restrict__ We,
    const float* __restrict__ be,
    float* __restrict__ ee_out, float* __restrict__ lsm_out,
    float* __restrict__ ei_out, int n_ee, int n_lsm, int n_ei) {
    int b = blockIdx.x;
    int tid = threadIdx.x;
    if (b < COUNT_BLOCKS) {
        int e = b * 256 + tid;
        if (e < N_EDGES) atomicAdd(&g_deg[ei[N_EDGES + e]], 1);
    } else if (b < COUNT_BLOCKS + EMBED_BLOCKS) {
        __shared__ float sW[256];
        __shared__ float sb[16];
        sW[tid] = Wn[tid];
        if (tid < 16) sb[tid] = bn[tid];
        __syncthreads();
        int n = (b - COUNT_BLOCKS) * 256 + tid;
        if (n >= N_NODES) return;
        float xi[16];
        const float4* xp = (const float4*)(x + (size_t)n * 16);
#pragma unroll
        for (int q = 0; q < 4; q++) {
            float4 v = xp[q];
            xi[4*q] = v.x; xi[4*q+1] = v.y; xi[4*q+2] = v.z; xi[4*q+3] = v.w;
        }
        float o[16];
#pragma unroll
        for (int d = 0; d < 16; d++) {
            float acc = sb[d];
#pragma unroll
            for (int k = 0; k < 16; k++) acc = fmaf(xi[k], sW[k*16+d], acc);
            o[d] = fmaxf(acc, 0.f);
        }
        float4* op = (float4*)(g_h0 + (size_t)n * 16);
#pragma unroll
        for (int q = 0; q < 4; q++)
            op[q] = make_float4(o[4*q], o[4*q+1], o[4*q+2], o[4*q+3]);
    } else if (b < COUNT_BLOCKS + EMBED_BLOCKS + EE_BLOCKS) {
        __shared__ float sW[256];
        __shared__ float sb[16];
        sW[tid] = We[tid];
        if (tid < 16) sb[tid] = be[tid];
        __syncthreads();
        int e = (b - COUNT_BLOCKS - EMBED_BLOCKS) * 256 + tid;
        if (e >= N_EDGES) return;
        float xi[16];
        const float4* xp = (const float4*)(ea + (size_t)e * 16);
#pragma unroll
        for (int q = 0; q < 4; q++) {
            float4 v = xp[q];
            xi[4*q] = v.x; xi[4*q+1] = v.y; xi[4*q+2] = v.z; xi[4*q+3] = v.w;
        }
        float v[16];
        float m = -1e30f;
#pragma unroll
        for (int d = 0; d < 16; d++) {
            float acc = sb[d];
#pragma unroll
            for (int k = 0; k < 16; k++) acc = fmaf(xi[k], sW[k*16+d], acc);
            v[d] = fmaxf(acc, 0.f);
            m = fmaxf(m, v[d]);
        }
        float s = 0.f;
#pragma unroll
        for (int d = 0; d < 16; d++) s += expf(v[d] - m);
        float ls = m + logf(s);
        if (e < n_ee) {
            float4* eo = (float4*)(ee_out + (size_t)e * 16);
#pragma unroll
            for (int q = 0; q < 4; q++)
                eo[q] = make_float4(v[4*q], v[4*q+1], v[4*q+2], v[4*q+3]);
        }
        if (e < n_lsm) {
            float4* lo = (float4*)(lsm_out + (size_t)e * 16);
#pragma unroll
            for (int q = 0; q < 4; q++)
                lo[q] = make_float4(v[4*q] - ls, v[4*q+1] - ls,
                                    v[4*q+2] - ls, v[4*q+3] - ls);
        }
    } else {
        int i = (b - COUNT_BLOCKS - EMBED_BLOCKS - EE_BLOCKS) * 256 + tid;
        if (i < n_ei) ei_out[i] = (float)ei[i];
    }
}

// ---------------- launch 1: prefix scan --------------------------------------
__global__ void __launch_bounds__(1024) k_scan() {
    __shared__ int sm[1024];
    int t = threadIdx.x;
    int base = t * 20;
    int vals[20];
    int local = 0;
#pragma unroll
    for (int i = 0; i < 20; i++) {
        int idx = base + i;
        vals[i] = (idx < N_NODES) ? g_deg[idx] : 0;
        local += vals[i];
    }
    sm[t] = local;
    __syncthreads();
    for (int off = 1; off < 1024; off <<= 1) {
        int v = (t >= off) ? sm[t - off] : 0;
        __syncthreads();
        sm[t] += v;
        __syncthreads();
    }
    int run = sm[t] - local;
#pragma unroll
    for (int i = 0; i < 20; i++) {
        int idx = base + i;
        if (idx < N_NODES) { g_off[idx] = run; run += vals[i]; g_cursor[idx] = 0; }
    }
    if (t == 0) g_off[N_NODES] = N_EDGES;
}

// ---------------- launch 2: fill sorted edge list + position map -------------
__global__ void k_fill(const int* __restrict__ ei) {
    int e = blockIdx.x * blockDim.x + threadIdx.x;
    if (e < N_EDGES) {
        int d = ei[N_EDGES + e];
        int pos = g_off[d] + atomicAdd(&g_cursor[d], 1);
        g_es[pos] = make_int2(e, ei[e]);
        g_pos[e] = pos;
    }
    if (e < N_NODES) g_deg[e] = 0;
}

// ---------------- launch 3: hid (sorted order) + B build ---------------------
#define HID_BLOCKS 6250
#define B_BLOCKS 256
__global__ void __launch_bounds__(256) k_prep2(
    const float* __restrict__ ea,
    const float* __restrict__ W1, const float* __restrict__ b1,
    const float* __restrict__ W2) {
    int b = blockIdx.x;
    int tid = threadIdx.x;
    if (b < HID_BLOCKS) {
        __shared__ float sEA[64 * 17];
        __shared__ float sW1[16 * 128];
        __shared__ float sB1[128];
        __shared__ int   sPos[64];
        int e0 = b * 64;
        for (int idx = tid; idx < 64 * 16; idx += 256) {
            int e = idx >> 4, k = idx & 15;
            sEA[e*17 + k] = ea[(size_t)(e0 + e)*16 + k];
        }
        for (int idx = tid; idx < 2048; idx += 256) sW1[idx] = W1[idx];
        if (tid < 128) sB1[tid] = b1[tid];
        if (tid < 64) sPos[tid] = g_pos[e0 + tid];
        __syncthreads();
        int el = tid >> 2;
        int p  = tid & 3;
        float a[16];
#pragma unroll
        for (int k = 0; k < 16; k++) a[k] = sEA[el*17 + k];
        float* outp = g_hid + (size_t)sPos[el] * 128 + p * 32;
#pragma unroll
        for (int uu = 0; uu < 32; uu += 4) {
            int ub = p*32 + uu;
            float c0 = sB1[ub+0], c1 = sB1[ub+1], c2 = sB1[ub+2], c3 = sB1[ub+3];
#pragma unroll
            for (int k = 0; k < 16; k++) {
                float av = a[k];
                const float* wr = &sW1[k*128 + ub];
                c0 = fmaf(av, wr[0], c0);
                c1 = fmaf(av, wr[1], c1);
                c2 = fmaf(av, wr[2], c2);
                c3 = fmaf(av, wr[3], c3);
            }
            *(float4*)(outp + uu) = make_float4(fmaxf(c0, 0.f), fmaxf(c1, 0.f),
                                                fmaxf(c2, 0.f), fmaxf(c3, 0.f));
        }
    } else {
        int idx = (b - HID_BLOCKS) * 256 + tid;
        int kj = idx >> 4, d = idx & 15;
        float v;
        if (kj < 2048) {
            int k = kj >> 4, j = kj & 15;
            v = W2[(size_t)k * 512 + (16 + j) * 16 + d];
        } else {
            int m = kj - 2048;
            int k = m >> 4, r = m & 15;
            v = W2[(size_t)k * 512 + r * 16 + d];
        }
        g_B[idx] = v;
    }
}

// ---------------- edge pass: streaming hid, pipelined -------------------------
#define EP_SMEM (8 * 32 * 68 * 4)
__global__ void __launch_bounds__(256, 2) k_edge_pass(int sin) {
    extern __shared__ float st[];
    const float* hin = (sin == 0) ? g_h0 : g_h1;
    int tid = threadIdx.x, wid = tid >> 5, l = tid & 31;
    int n = blockIdx.x * 8 + wid;

    int start = g_off[n], end = g_off[n + 1];

    ull T[4][8];
#pragma unroll
    for (int kk = 0; kk < 4; kk++)
#pragma unroll
        for (int q = 0; q < 8; q++) T[kk][q] = 0ull;
    ull Hs[8];
#pragma unroll
    for (int q = 0; q < 8; q++) Hs[q] = 0ull;
    float hs0 = 0.f, hs1 = 0.f, hs2 = 0.f, hs3 = 0.f;

    if (start < end) {
        int last = end - 1;
        // current-iteration data (hid now streams: sorted position == loop index)
        float4 hidC = *(const float4*)(g_hid + (size_t)start * 128 + 4*l);
        int2 esC = g_es[start];
        const ulonglong2* hp = (const ulonglong2*)(hin + (size_t)esC.y * 16);
        ulonglong2 ha = hp[0], hb = hp[1], hc = hp[2], hd = hp[3];
        ull hC[8] = {ha.x, ha.y, hb.x, hb.y, hc.x, hc.y, hd.x, hd.y};

        for (int pos = start; pos < end; pos++) {
            int pn = pos + 1 <= last ? pos + 1 : last;
            // issue next-iteration loads first
            float4 hidN = *(const float4*)(g_hid + (size_t)pn * 128 + 4*l);
            int2 esN = g_es[pn];
            const ulonglong2* hp2 = (const ulonglong2*)(hin + (size_t)esN.y * 16);
            ulonglong2 na = hp2[0], nb = hp2[1], nc = hp2[2], nd = hp2[3];
            // compute with current
            float4 hd4 = hidC;
#pragma unroll
            for (int q = 0; q < 8; q++) Hs[q] = add2(Hs[q], hC[q]);
            hs0 += hd4.x; hs1 += hd4.y; hs2 += hd4.z; hs3 += hd4.w;
            ull p0 = pack2(hd4.x, hd4.x), pq1 = pack2(hd4.y, hd4.y);
            ull pq2 = pack2(hd4.z, hd4.z), pq3 = pack2(hd4.w, hd4.w);
#pragma unroll
            for (int q = 0; q < 8; q++) {
                T[0][q] = fma2(p0, hC[q], T[0][q]);
                T[1][q] = fma2(pq1, hC[q], T[1][q]);
                T[2][q] = fma2(pq2, hC[q], T[2][q]);
                T[3][q] = fma2(pq3, hC[q], T[3][q]);
            }
            // rotate
            hidC = hidN;
            hC[0] = na.x; hC[1] = na.y; hC[2] = nb.x; hC[3] = nb.y;
            hC[4] = nc.x; hC[5] = nc.y; hC[6] = nd.x; hC[7] = nd.y;
        }
    }

    // write T via warp-local smem transpose (coalesced)
    float* W = st + wid * (32 * 68) + l * 68;
#pragma unroll
    for (int kk = 0; kk < 4; kk++) {
        float t[16];
#pragma unroll
        for (int q = 0; q < 8; q++) unpack2(T[kk][q], t[2*q], t[2*q+1]);
#pragma unroll
        for (int f = 0; f < 4; f++)
            *(float4*)&W[kk*16 + 4*f] = make_float4(t[4*f], t[4*f+1], t[4*f+2], t[4*f+3]);
    }
    __syncwarp();
    float* Wbase = st + wid * (32 * 68);
    float* Trow = g_S + (size_t)n * KT;
#pragma unroll
    for (int s = 0; s < 16; s++) {
        int idx = s * 128 + 4 * l;
        float4 v = *(float4*)&Wbase[(idx >> 6) * 68 + (idx & 63)];
        *(float4*)&Trow[idx] = v;
    }
    *(float4*)&g_Hsum[(size_t)n * 128 + 4*l] = make_float4(hs0, hs1, hs2, hs3);
    if (l == 0) {
#pragma unroll
        for (int q = 0; q < 8; q++) {
            float a, b; unpack2(Hs[q], a, b);
            g_HsJ[n * 16 + 2*q]     = a;
            g_HsJ[n * 16 + 2*q + 1] = b;
        }
    }
}

// ---------------- epilogue: seed hout with non-GEMM terms --------------------
__global__ void k_epi(int sin, int sout, float* ext,
                      const float* __restrict__ root,
                      const float* __restrict__ b2,
                      const float* __restrict__ bias) {
    __shared__ float sR[256];
    __shared__ float sB2[512];
    __shared__ float sBi[16];
    const float* hin = pick_cbuf(sin, ext);
    float* hout = pick_buf(sout, ext);
    int tid = threadIdx.x;
    sR[tid] = root[tid];
    sB2[tid] = b2[tid];
    sB2[256 + tid] = b2[256 + tid];
    if (tid < 16) sBi[tid] = bias[tid];
    __syncthreads();
    int n = blockIdx.x * 256 + tid;
    if (n >= N_NODES) return;
    float h[16], hs[16];
    const float4* hp = (const float4*)(hin + (size_t)n * 16);
    const float4* sp = (const float4*)(g_HsJ + (size_t)n * 16);
#pragma unroll
    for (int q = 0; q < 4; q++) {
        float4 a = hp[q]; h[4*q] = a.x; h[4*q+1] = a.y; h[4*q+2] = a.z; h[4*q+3] = a.w;
        float4 b = sp[q]; hs[4*q] = b.x; hs[4*q+1] = b.y; hs[4*q+2] = b.z; hs[4*q+3] = b.w;
    }
    float dg = (float)(g_off[n+1] - g_off[n]);
    float o[16];
#pragma unroll
    for (int d = 0; d < 16; d++) o[d] = sBi[d];
#pragma unroll
    for (int r = 0; r < 16; r++) {
        float hr = h[r], hdg = h[r] * dg, hj = hs[r];
#pragma unroll
        for (int d = 0; d < 16; d++) {
            o[d] = fmaf(hr, sR[r*16+d], o[d]);
            o[d] = fmaf(hdg, sB2[r*16+d], o[d]);
            o[d] = fmaf(hj, sB2[256 + r*16+d], o[d]);
        }
    }
    float4* op = (float4*)(hout + (size_t)n * 16);
#pragma unroll
    for (int q = 0; q < 4; q++)
        op[q] = make_float4(o[4*q], o[4*q+1], o[4*q+2], o[4*q+3]);
}

// ---------------- GEMM: hout += [T | synth(Hsum⊗h)] @ B ----------------------
// register double-buffering: next chunk's A/B tiles load during compute.
#define GT 256
#define SA_P 129
__global__ void __launch_bounds__(GT) k_gemm(int sin, int sout, float* ext) {
    __shared__ __align__(16) float sA[64 * SA_P];
    __shared__ __align__(16) float sB[64 * 16];
    const float* hin = pick_cbuf(sin, ext);
    float* hout = pick_buf(sout, ext);
    int tid = threadIdx.x;
    int n0 = blockIdx.x * 128;
    int ks = blockIdx.y;                  // 0..7, chunks ks*8 .. ks*8+7
    int nn = tid & 127, half = tid >> 7;
    ull acc[4] = {0ull, 0ull, 0ull, 0ull};

    float4 r[8];
    float4 rb;
    auto load_chunk = [&](int c) {
        int k0 = c * 64;
#pragma unroll
        for (int j = 0; j < 8; j++) {
            int i = tid + j * 256;
            int an = i >> 4, q = i & 15;
            int gn = n0 + an;
            float4 v = make_float4(0.f, 0.f, 0.f, 0.f);
            if (gn < N_NODES) {
                if (c < 32) {
                    v = *(const float4*)(g_S + (size_t)gn * KT + k0 + 4*q);
                } else {
                    int m = k0 - 2048 + 4*q;
                    float hsv = g_Hsum[(size_t)gn * 128 + (m >> 4)];
                    float4 h4 = ((const float4*)(hin + (size_t)gn * 16))[(m & 15) >> 2];
                    v = make_float4(hsv*h4.x, hsv*h4.y, hsv*h4.z, hsv*h4.w);
                }
            }
            r[j] = v;
        }
        rb = ((const float4*)(g_B + (size_t)k0 * 16))[tid];
    };

    load_chunk(ks * 8);
    for (int ci = 0; ci < 8; ci++) {
        __syncthreads();
#pragma unroll
        for (int j = 0; j < 8; j++) {
            int i = tid + j * 256;
            int an = i >> 4, q = i & 15;
            sA[(4*q + 0) * SA_P + an] = r[j].x;
            sA[(4*q + 1) * SA_P + an] = r[j].y;
            sA[(4*q + 2) * SA_P + an] = r[j].z;
            sA[(4*q + 3) * SA_P + an] = r[j].w;
        }
        ((float4*)sB)[tid] = rb;
        __syncthreads();
        if (ci < 7) load_chunk(ks * 8 + ci + 1);   // overlaps with compute below
#pragma unroll 8
        for (int k = 0; k < 64; k++) {
            float a = sA[k * SA_P + nn];
            ull a2 = pack2(a, a);
            ulonglong2 b01 = *(const ulonglong2*)&sB[k * 16 + 8 * half];
            ulonglong2 b23 = *(const ulonglong2*)&sB[k * 16 + 8 * half + 4];
            acc[0] = fma2(a2, b01.x, acc[0]);
            acc[1] = fma2(a2, b01.y, acc[1]);
            acc[2] = fma2(a2, b23.x, acc[2]);
            acc[3] = fma2(a2, b23.y, acc[3]);
        }
    }

    int n = n0 + nn;
    if (n < N_NODES) {
        float o[8];
        unpack2(acc[0], o[0], o[1]);
        unpack2(acc[1], o[2], o[3]);
        unpack2(acc[2], o[4], o[5]);
        unpack2(acc[3], o[6], o[7]);
        float* dst = hout + (size_t)n * 16 + 8 * half;
#pragma unroll
        for (int j = 0; j < 8; j++) atomicAdd(dst + j, o[j]);
    }
}

// ---------------- launch -------------------------------------------------------
extern "C" void kernel_launch(void* const* d_in, const int* in_sizes, int n_in,
                              void* d_out, int out_size) {
    const float* x     = (const float*)d_in[0];
    const int*   ei    = (const int*)d_in[1];
    const float* ea    = (const float*)d_in[2];
    const float* Wn    = (const float*)d_in[3];
    const float* bn    = (const float*)d_in[4];
    const float* We    = (const float*)d_in[5];
    const float* be    = (const float*)d_in[6];
    const float* W1    = (const float*)d_in[7];
    const float* b1    = (const float*)d_in[8];
    const float* W2    = (const float*)d_in[9];
    const float* b2    = (const float*)d_in[10];
    const float* root1 = (const float*)d_in[11];
    const float* bias1 = (const float*)d_in[12];
    const float* root2 = (const float*)d_in[13];
    const float* bias2 = (const float*)d_in[14];

    float* out = (float*)d_out;
    size_t cap = (size_t)out_size;

    size_t ei_slots = (cap == 13120000) ? 0 : 2ull * N_EDGES;
    size_t off_h   = 0;
    size_t off_ei  = off_h + (size_t)N_NODES * 16;
    size_t off_ee  = off_ei + ei_slots;
    size_t off_lsm = off_ee + (size_t)N_EDGES * 16;
    auto avail = [&](size_t off) -> size_t { return off < cap ? cap - off : 0; };

    float* out_h   = out + off_h;
    float* out_ei  = out + off_ei;
    float* out_ee  = out + off_ee;
    float* out_lsm = out + off_lsm;

    bool h_fits = avail(off_h) >= (size_t)N_NODES * 16;
    int  n_ei   = ei_slots ? (int)min((size_t)(2 * N_EDGES), avail(off_ei)) : 0;
    int  n_ee   = (int)min((size_t)N_EDGES, avail(off_ee) / 16);
    int  n_lsm  = (int)min((size_t)N_EDGES, avail(off_lsm) / 16);
    int  sout2  = h_fits ? 2 : 0;

    cudaFuncSetAttribute(k_edge_pass, cudaFuncAttributeMaxDynamicSharedMemorySize,
                         EP_SMEM);

    // 0: fused front: degree count + node embed + edge embed/lsm + ei copy
    k_front<<<FRONT_BLOCKS, 256>>>(ei, x, Wn, bn, ea, We, be,
                                   out_ee, out_lsm, out_ei, n_ee, n_lsm, n_ei);
    // 1: prefix scan (re-zeros g_cursor)
    k_scan<<<1, 1024>>>();
    // 2: fill sorted edge list + position map (re-zeros g_deg)
    k_fill<<<COUNT_BLOCKS, 256>>>(ei);
    // 3: hid GEMM (sorted order) + B build   [profiled]
    k_prep2<<<HID_BLOCKS + B_BLOCKS, 256>>>(ea, W1, b1, W2);

    dim3 gg((N_NODES + 127) / 128, 8);
    // layer 1
    k_edge_pass<<<N_NODES / 8, 256, EP_SMEM>>>(0);
    k_epi<<<(N_NODES + 255) / 256, 256>>>(0, 1, out_h, root1, b2, bias1);
    k_gemm<<<gg, GT>>>(0, 1, out_h);
    // layer 2
    k_edge_pass<<<N_NODES / 8, 256, EP_SMEM>>>(1);
    k_epi<<<(N_NODES + 255) / 256, 256>>>(1, sout2, out_h, root2, b2, bias2);
    k_gemm<<<gg, GT>>>(1, sout2, out_h);
}